// round 3
// baseline (speedup 1.0000x reference)
#include <cuda_runtime.h>

#define H       2048
#define E       64
#define M_TILE  64
#define K_TILE  32
#define NTHREADS 128

// Prep-kernel outputs (static device scratch; no allocations allowed)
__device__ float g_wgT[H * E];   // [h][e] = gate[e][h] * ln_weight[h]
__device__ float g_c[E];         // sum_h gate[e][h]*w[h]
__device__ float g_d[E];         // sum_h ln_bias[h]*gate[e][h]

// ---------------------------------------------------------------------------
// prep: build transposed, ln_weight-folded gate matrix + per-expert constants
// ---------------------------------------------------------------------------
__global__ void prep_kernel(const float* __restrict__ gate,
                            const float* __restrict__ w,
                            const float* __restrict__ b) {
    int e = blockIdx.x;
    int t = threadIdx.x;
    float sc = 0.f, sd = 0.f;
    for (int h = t; h < H; h += 256) {
        float gv = gate[e * H + h];
        float p  = gv * w[h];
        g_wgT[h * E + e] = p;
        sc += p;
        sd += b[h] * gv;
    }
    __shared__ float rs[256], rd[256];
    rs[t] = sc; rd[t] = sd;
    __syncthreads();
    for (int s = 128; s > 0; s >>= 1) {
        if (t < s) { rs[t] += rs[t + s]; rd[t] += rd[t + s]; }
        __syncthreads();
    }
    if (t == 0) { g_c[e] = rs[0]; g_d[e] = rd[0]; }
}

// packed f32x2 FMA (Blackwell): d = a*b + d elementwise on float pairs
__device__ __forceinline__ void ffma2(unsigned long long& d,
                                      unsigned long long a,
                                      unsigned long long b) {
    asm("fma.rn.f32x2 %0, %1, %2, %0;" : "+l"(d) : "l"(a), "l"(b));
}

// ---------------------------------------------------------------------------
// main: fused stats + GEMM + softmax + top2
// grid = n_rows/64 blocks, 128 threads
// ---------------------------------------------------------------------------
__global__ __launch_bounds__(NTHREADS)
void router_kernel(const float* __restrict__ X, float* __restrict__ out,
                   int n_rows) {
    __shared__ float s_xd[K_TILE][2 * M_TILE];  // x duplicated pairs: 16 KB
    __shared__ float s_w[K_TILE * E];           // 8 KB
    __shared__ float s_mu[M_TILE], s_rstd[M_TILE];
    __shared__ float s_c[E], s_d[E];

    const int t  = threadIdx.x;
    const int row_base = blockIdx.x * M_TILE;
    const int tx = t & 7;       // expert group
    const int ty = t >> 3;      // row group (0..15)
    const int e0 = tx * 8;
    const int r0 = ty * 4;

    if (t < E) { s_c[t] = g_c[t]; s_d[t] = g_d[t]; }

    // loader mapping: 2 threads per row, 16 consecutive floats each
    const int lrow = t >> 1;
    const int lk   = (t & 1) * 16;
    const float4* xg = (const float4*)(X + (size_t)(row_base + lrow) * H + lk);
    const float4* wg = (const float4*)g_wgT;   // tile kt starts at float4 idx kt*512

    float4 xr[4], wr[4];
#pragma unroll
    for (int i = 0; i < 4; i++) xr[i] = xg[i];
#pragma unroll
    for (int i = 0; i < 4; i++) wr[i] = wg[t + 128 * i];

    unsigned long long acc[4][4];
#pragma unroll
    for (int j = 0; j < 4; j++)
#pragma unroll
        for (int p = 0; p < 4; p++) acc[j][p] = 0ull;

    float sum = 0.f, sumsq = 0.f;

    const int NT = H / K_TILE;  // 64
    for (int kt = 0; kt < NT; ++kt) {
        // row stats from the registers we're about to store
#pragma unroll
        for (int i = 0; i < 4; i++) {
            sum   += xr[i].x + xr[i].y + xr[i].z + xr[i].w;
            sumsq += xr[i].x * xr[i].x + xr[i].y * xr[i].y +
                     xr[i].z * xr[i].z + xr[i].w * xr[i].w;
        }
        __syncthreads();
        // store x duplicated (k-transposed)
#pragma unroll
        for (int i = 0; i < 4; i++) {
            int kb = lk + 4 * i;
            *(float2*)&s_xd[kb + 0][2 * lrow] = make_float2(xr[i].x, xr[i].x);
            *(float2*)&s_xd[kb + 1][2 * lrow] = make_float2(xr[i].y, xr[i].y);
            *(float2*)&s_xd[kb + 2][2 * lrow] = make_float2(xr[i].z, xr[i].z);
            *(float2*)&s_xd[kb + 3][2 * lrow] = make_float2(xr[i].w, xr[i].w);
        }
        float4* sw4 = (float4*)s_w;
#pragma unroll
        for (int i = 0; i < 4; i++) sw4[t + 128 * i] = wr[i];
        __syncthreads();

        // prefetch next tile
        if (kt + 1 < NT) {
            const float4* xgn = xg + (size_t)(kt + 1) * 8;
            const float4* wgn = wg + (size_t)(kt + 1) * 512;
#pragma unroll
            for (int i = 0; i < 4; i++) xr[i] = xgn[i];
#pragma unroll
            for (int i = 0; i < 4; i++) wr[i] = wgn[t + 128 * i];
        }

        // compute: 4 rows x 8 experts per thread, f32x2-packed along experts
#pragma unroll 8
        for (int kk = 0; kk < K_TILE; ++kk) {
            ulonglong2 xa = *(const ulonglong2*)&s_xd[kk][2 * r0];
            ulonglong2 xb = *(const ulonglong2*)&s_xd[kk][2 * r0 + 4];
            ulonglong2 wa = *(const ulonglong2*)&s_w[kk * E + e0];
            ulonglong2 wb = *(const ulonglong2*)&s_w[kk * E + e0 + 4];
            ffma2(acc[0][0], xa.x, wa.x); ffma2(acc[0][1], xa.x, wa.y);
            ffma2(acc[0][2], xa.x, wb.x); ffma2(acc[0][3], xa.x, wb.y);
            ffma2(acc[1][0], xa.y, wa.x); ffma2(acc[1][1], xa.y, wa.y);
            ffma2(acc[1][2], xa.y, wb.x); ffma2(acc[1][3], xa.y, wb.y);
            ffma2(acc[2][0], xb.x, wa.x); ffma2(acc[2][1], xb.x, wa.y);
            ffma2(acc[2][2], xb.x, wb.x); ffma2(acc[2][3], xb.x, wb.y);
            ffma2(acc[3][0], xb.y, wa.x); ffma2(acc[3][1], xb.y, wa.y);
            ffma2(acc[3][2], xb.y, wb.x); ffma2(acc[3][3], xb.y, wb.y);
        }
    }

    // finalize row stats (2 loader threads per row)
    sum   += __shfl_xor_sync(0xffffffffu, sum, 1);
    sumsq += __shfl_xor_sync(0xffffffffu, sumsq, 1);
    if ((t & 1) == 0) {
        float mu  = sum * (1.0f / H);
        float var = sumsq * (1.0f / H) - mu * mu;
        s_mu[lrow]   = mu;
        s_rstd[lrow] = 1.0f / sqrtf(var + 1e-5f);
    }
    __syncthreads();

    float* out_p = out;                         // (N,2) normalized top-2 probs
    float* out_i = out + (size_t)n_rows * 2;    // (N,2) indices (as float)
    float* out_l = out + (size_t)n_rows * 4;    // (N,64) logits

#pragma unroll
    for (int j = 0; j < 4; j++) {
        int row  = r0 + j;
        int grow = row_base + row;
        float mu   = s_mu[row];
        float rstd = s_rstd[row];
        float l[8];
#pragma unroll
        for (int p = 0; p < 4; p++) {
            unsigned long long v = acc[j][p];
            l[2 * p]     = __uint_as_float((unsigned int)(v & 0xffffffffull));
            l[2 * p + 1] = __uint_as_float((unsigned int)(v >> 32));
        }
#pragma unroll
        for (int i = 0; i < 8; i++) {
            float lv = rstd * (l[i] - mu * s_c[e0 + i]) + s_d[e0 + i];
            l[i] = fminf(fmaxf(lv, -10.0f), 10.0f);
        }
        *(float4*)&out_l[(size_t)grow * 64 + e0]     = make_float4(l[0], l[1], l[2], l[3]);
        *(float4*)&out_l[(size_t)grow * 64 + e0 + 4] = make_float4(l[4], l[5], l[6], l[7]);

        // row max over 64 (8 local + width-8 butterfly)
        float m = l[0];
#pragma unroll
        for (int i = 1; i < 8; i++) m = fmaxf(m, l[i]);
#pragma unroll
        for (int s8 = 4; s8; s8 >>= 1)
            m = fmaxf(m, __shfl_xor_sync(0xffffffffu, m, s8));

        float ev[8];
        float s = 0.f;
#pragma unroll
        for (int i = 0; i < 8; i++) { ev[i] = expf(l[i] - m); s += ev[i]; }
#pragma unroll
        for (int s8 = 4; s8; s8 >>= 1)
            s += __shfl_xor_sync(0xffffffffu, s, s8);

        // local top-2 (clip to [1e-4, 1] first, as reference does before top_k)
        float v1 = -1.f, v2 = -1.f; int i1 = 0, i2 = 0;
#pragma unroll
        for (int i = 0; i < 8; i++) {
            float p = ev[i] / s;
            p = fminf(fmaxf(p, 1e-4f), 1.0f);
            int gi = e0 + i;
            if (p > v1) { v2 = v1; i2 = i1; v1 = p; i1 = gi; }
            else if (p > v2) { v2 = p; i2 = gi; }
        }
        // butterfly merge of top-2 lists, tie-break on lower index (jax top_k)
#pragma unroll
        for (int s8 = 4; s8; s8 >>= 1) {
            float u1 = __shfl_xor_sync(0xffffffffu, v1, s8);
            int   j1 = __shfl_xor_sync(0xffffffffu, i1, s8);
            float u2 = __shfl_xor_sync(0xffffffffu, v2, s8);
            int   j2 = __shfl_xor_sync(0xffffffffu, i2, s8);
            bool afirst = (v1 > u1) || (v1 == u1 && i1 < j1);
            float w1 = afirst ? v1 : u1;  int k1 = afirst ? i1 : j1;
            float ca = afirst ? v2 : u2;  int kca = afirst ? i2 : j2;  // winner's 2nd
            float cb = afirst ? u1 : v1;  int kcb = afirst ? j1 : i1;  // loser's 1st
            bool bsec = (cb > ca) || (cb == ca && kcb < kca);
            float w2 = bsec ? cb : ca;    int k2 = bsec ? kcb : kca;
            v1 = w1; i1 = k1; v2 = w2; i2 = k2;
        }
        if (tx == 0) {
            float ps = fmaxf(v1 + v2, 1e-4f);
            out_p[(size_t)grow * 2 + 0] = v1 / ps;
            out_p[(size_t)grow * 2 + 1] = v2 / ps;
            out_i[(size_t)grow * 2 + 0] = (float)i1;
            out_i[(size_t)grow * 2 + 1] = (float)i2;
        }
    }
}

extern "C" void kernel_launch(void* const* d_in, const int* in_sizes, int n_in,
                              void* d_out, int out_size) {
    const float* X = (const float*)d_in[0];   // hidden_states (4,4096,2048)
    const float* w = (const float*)d_in[1];   // ln_weight (2048)
    const float* b = (const float*)d_in[2];   // ln_bias (2048)
    const float* g = (const float*)d_in[3];   // gate_weight (64,2048)
    int n_rows = in_sizes[0] / H;             // 16384

    prep_kernel<<<E, 256>>>(g, w, b);
    router_kernel<<<n_rows / M_TILE, NTHREADS>>>(X, (float*)d_out, n_rows);
}